// round 8
// baseline (speedup 1.0000x reference)
#include <cuda_runtime.h>
#include <math.h>

// Problem shapes (fixed by the reference)
#define NB 8192          // batch
#define SS 10            // senses
#define HH 1024          // hidden
#define THREADS 256
#define NBLOCKS 740      // >= one full wave at any plausible residency; tickets balance
#define ALPHA_ROWS 16200 // 2700*6
#define ALPHA_CHUNKS 64
#define ALPHA_CHUNK 254  // 64*254 = 16256 >= 16200
#define NTICKETS (NB + ALPHA_CHUNKS)

// Scratch (device globals: no allocation allowed anywhere)
__device__ float g_margin_part[NB];
__device__ float g_alpha_part[ALPHA_CHUNKS];
__device__ unsigned int g_ticket;  // zero-init; self-resetting
__device__ unsigned int g_done;    // zero-init; self-resetting

__global__ __launch_bounds__(THREADS)
void marginal_loss_fused(const float* __restrict__ sentence,
                         const float* __restrict__ gloss,
                         const float* __restrict__ alpha,
                         const int*   __restrict__ mask,
                         const int*   __restrict__ sids,
                         float* __restrict__ out, int out_size)
{
    const int lane = threadIdx.x & 31;

    // ---- dynamic ticket loop: perfect balance across SMs ----
    for (;;) {
        unsigned int t;
        if (lane == 0) t = atomicAdd(&g_ticket, 1u);
        t = __shfl_sync(0xffffffffu, t, 0);
        if (t >= NTICKETS) break;

        if (t < NB) {
            // ---- margin row t: one warp, j-outer / sense-inner for MLP=10 ----
            const int b = (int)t;
            const float4* __restrict__ srow =
                reinterpret_cast<const float4*>(sentence + (size_t)b * HH);
            const float4* __restrict__ gbase =
                reinterpret_cast<const float4*>(gloss + (size_t)b * SS * HH);

            float acc[SS];
            #pragma unroll
            for (int s = 0; s < SS; ++s) acc[s] = 0.0f;

            #pragma unroll
            for (int j = 0; j < 8; ++j) {
                const int idx = lane + j * 32;        // float4 index within a row
                const float4 sv = srow[idx];
                // 10 independent 128B-coalesced loads in flight per thread
                #pragma unroll
                for (int s = 0; s < SS; ++s) {
                    float4 g = gbase[s * (HH / 4) + idx];
                    float d0 = sv.x - g.x + 1e-6f;
                    float d1 = sv.y - g.y + 1e-6f;
                    float d2 = sv.z - g.z + 1e-6f;
                    float d3 = sv.w - g.w + 1e-6f;
                    float a = acc[s];
                    a = fmaf(d0, d0, a);
                    a = fmaf(d1, d1, a);
                    a = fmaf(d2, d2, a);
                    a = fmaf(d3, d3, a);
                    acc[s] = a;
                }
            }

            #pragma unroll
            for (int s = 0; s < SS; ++s) {
                float v = acc[s];
                #pragma unroll
                for (int off = 16; off > 0; off >>= 1)
                    v += __shfl_xor_sync(0xffffffffu, v, off);
                acc[s] = v;
            }

            if (lane == 0) {
                const int sid = sids[b];
                float pos  = 0.0f;
                float minv = 1e30f;   // first strict-< win == argmin first-index tie rule
                float neg  = 0.0f;
                #pragma unroll
                for (int s = 0; s < SS; ++s) {
                    float ds = sqrtf(acc[s]);
                    if (s == sid) pos = ds;
                    bool valid = (mask[b * SS + s] != 0) && (s != sid);
                    float m = valid ? ds : 10.0f;          // SENTINEL
                    if (m < minv) { minv = m; neg = ds; }  // carry REAL distance at argmin
                }
                g_margin_part[b] = fmaxf(pos - neg + 0.5f, 0.0f);
            }
        } else {
            // ---- alpha chunk ----
            const int c     = (int)(t - NB);
            const int start = c * ALPHA_CHUNK;
            const int end   = min(start + ALPHA_CHUNK, ALPHA_ROWS);
            float part = 0.0f;
            for (int r = start + lane; r < end; r += 32) {
                const float* __restrict__ row = alpha + (size_t)r * 10;
                float s0 = 0.0f, mx = -1e30f;
                #pragma unroll
                for (int k = 0; k < 10; ++k) {
                    float v = row[k];
                    s0 += v;
                    mx = fmaxf(mx, v);
                }
                // row_sum==0 -> tmp=ones -> max=1 -> |1-1| = 0
                part += (s0 == 0.0f) ? 0.0f : fabsf(mx - 1.0f);
            }
            #pragma unroll
            for (int off = 16; off > 0; off >>= 1)
                part += __shfl_xor_sync(0xffffffffu, part, off);
            if (lane == 0) g_alpha_part[c] = part;
        }
    }

    // ---- completion-counter fused finalize (last block only) ----
    __shared__ bool s_last;
    __syncthreads();
    if (threadIdx.x == 0) {
        __threadfence();
        unsigned int d = atomicAdd(&g_done, 1u);
        s_last = (d == (unsigned int)(gridDim.x - 1));
    }
    __syncthreads();
    if (!s_last) return;

    __shared__ float sh[THREADS];

    // margin sum, fixed order -> bit-deterministic
    float m = 0.0f;
    for (int i = threadIdx.x; i < NB; i += THREADS) m += g_margin_part[i];
    sh[threadIdx.x] = m;
    __syncthreads();
    #pragma unroll
    for (int off = THREADS / 2; off > 0; off >>= 1) {
        if (threadIdx.x < off) sh[threadIdx.x] += sh[threadIdx.x + off];
        __syncthreads();
    }
    float margin = sh[0];
    __syncthreads();

    // alpha sum
    float a = (threadIdx.x < ALPHA_CHUNKS) ? g_alpha_part[threadIdx.x] : 0.0f;
    sh[threadIdx.x] = a;
    __syncthreads();
    #pragma unroll
    for (int off = THREADS / 2; off > 0; off >>= 1) {
        if (threadIdx.x < off) sh[threadIdx.x] += sh[threadIdx.x + off];
        __syncthreads();
    }
    float alpha_term = sh[0];

    if (threadIdx.x == 0) {
        float loss = margin * 0.875f + alpha_term * 0.125f;
        out[0] = loss;
        if (out_size > 1) out[1] = margin;
        if (out_size > 2) out[2] = alpha_term;
        // self-reset for next graph replay (stream order guarantees visibility)
        g_ticket = 0u;
        g_done   = 0u;
    }
}

extern "C" void kernel_launch(void* const* d_in, const int* in_sizes, int n_in,
                              void* d_out, int out_size)
{
    // Identify inputs robustly by element count (all distinct):
    //   sentence  8192*1024    = 8388608  (f32)
    //   all_gloss 8192*10*1024 = 83886080 (f32)
    //   alpha     2700*6*10    = 162000   (f32)
    //   sense_mask 8192*10     = 81920    (i32)
    //   sense_ids 8192         = 8192     (i32)
    const float* sentence = nullptr;
    const float* gloss    = nullptr;
    const float* alpha    = nullptr;
    const int*   mask     = nullptr;
    const int*   sids     = nullptr;
    for (int i = 0; i < n_in; ++i) {
        switch (in_sizes[i]) {
            case 8388608:  sentence = (const float*)d_in[i]; break;
            case 83886080: gloss    = (const float*)d_in[i]; break;
            case 162000:   alpha    = (const float*)d_in[i]; break;
            case 81920:    mask     = (const int*)  d_in[i]; break;
            case 8192:     sids     = (const int*)  d_in[i]; break;
            default: break;
        }
    }

    marginal_loss_fused<<<NBLOCKS, THREADS>>>(sentence, gloss, alpha, mask, sids,
                                              (float*)d_out, out_size);
}

// round 9
// speedup vs baseline: 1.0935x; 1.0935x over previous
#include <cuda_runtime.h>
#include <math.h>

// Problem shapes (fixed by the reference)
#define NB 8192          // batch
#define SS 10            // senses
#define HH 1024          // hidden
#define THREADS 256
#define NBLOCKS 740      // tickets balance any residency; >= one full wave
#define ALPHA_ROWS 16200 // 2700*6
#define ALPHA_CHUNKS 64
#define ALPHA_CHUNK 254  // 64*254 = 16256 >= 16200
#define NTICKETS (NB + ALPHA_CHUNKS)

// Scratch (device globals: no allocation allowed anywhere)
__device__ float g_margin_part[NB];
__device__ float g_alpha_part[ALPHA_CHUNKS];
__device__ unsigned int g_ticket;  // zero-init; self-resetting
__device__ unsigned int g_done;    // zero-init; self-resetting

// (256,3): 85-reg budget -> room for 11 in-flight float4 loads, still 3 blocks/SM
__global__ __launch_bounds__(THREADS, 3)
void marginal_loss_fused(const float* __restrict__ sentence,
                         const float* __restrict__ gloss,
                         const float* __restrict__ alpha,
                         const int*   __restrict__ mask,
                         const int*   __restrict__ sids,
                         float* __restrict__ out, int out_size)
{
    const int lane = threadIdx.x & 31;

    // ---- dynamic ticket loop: perfect balance across SMs ----
    for (;;) {
        unsigned int t;
        if (lane == 0) t = atomicAdd(&g_ticket, 1u);
        t = __shfl_sync(0xffffffffu, t, 0);
        if (t >= NTICKETS) break;

        if (t < NB) {
            // ---- margin row t: one warp; per j-step batch ALL 11 loads ----
            const int b = (int)t;
            const float4* __restrict__ srow =
                reinterpret_cast<const float4*>(sentence + (size_t)b * HH);
            const float4* __restrict__ gbase =
                reinterpret_cast<const float4*>(gloss + (size_t)b * SS * HH);

            float acc[SS];
            #pragma unroll
            for (int s = 0; s < SS; ++s) acc[s] = 0.0f;

            #pragma unroll
            for (int j = 0; j < 8; ++j) {
                const int idx = lane + j * 32;        // float4 index within a row

                // phase 1: issue 11 independent LDG.128 (front-batched by ptxas
                // because g[] is consumed as a whole below)
                float4 sv = srow[idx];
                float4 g[SS];
                #pragma unroll
                for (int s = 0; s < SS; ++s)
                    g[s] = gbase[s * (HH / 4) + idx];

                // phase 2: consume
                #pragma unroll
                for (int s = 0; s < SS; ++s) {
                    float d0 = sv.x - g[s].x + 1e-6f;
                    float d1 = sv.y - g[s].y + 1e-6f;
                    float d2 = sv.z - g[s].z + 1e-6f;
                    float d3 = sv.w - g[s].w + 1e-6f;
                    float a = acc[s];
                    a = fmaf(d0, d0, a);
                    a = fmaf(d1, d1, a);
                    a = fmaf(d2, d2, a);
                    a = fmaf(d3, d3, a);
                    acc[s] = a;
                }
            }

            #pragma unroll
            for (int s = 0; s < SS; ++s) {
                float v = acc[s];
                #pragma unroll
                for (int off = 16; off > 0; off >>= 1)
                    v += __shfl_xor_sync(0xffffffffu, v, off);
                acc[s] = v;
            }

            if (lane == 0) {
                const int sid = sids[b];
                float pos  = 0.0f;
                float minv = 1e30f;   // first strict-< win == argmin first-index tie rule
                float neg  = 0.0f;
                #pragma unroll
                for (int s = 0; s < SS; ++s) {
                    float ds = sqrtf(acc[s]);
                    if (s == sid) pos = ds;
                    bool valid = (mask[b * SS + s] != 0) && (s != sid);
                    float m = valid ? ds : 10.0f;          // SENTINEL
                    if (m < minv) { minv = m; neg = ds; }  // carry REAL distance at argmin
                }
                g_margin_part[b] = fmaxf(pos - neg + 0.5f, 0.0f);
            }
        } else {
            // ---- alpha chunk ----
            const int c     = (int)(t - NB);
            const int start = c * ALPHA_CHUNK;
            const int end   = min(start + ALPHA_CHUNK, ALPHA_ROWS);
            float part = 0.0f;
            for (int r = start + lane; r < end; r += 32) {
                const float* __restrict__ row = alpha + (size_t)r * 10;
                float s0 = 0.0f, mx = -1e30f;
                #pragma unroll
                for (int k = 0; k < 10; ++k) {
                    float v = row[k];
                    s0 += v;
                    mx = fmaxf(mx, v);
                }
                // row_sum==0 -> tmp=ones -> max=1 -> |1-1| = 0
                part += (s0 == 0.0f) ? 0.0f : fabsf(mx - 1.0f);
            }
            #pragma unroll
            for (int off = 16; off > 0; off >>= 1)
                part += __shfl_xor_sync(0xffffffffu, part, off);
            if (lane == 0) g_alpha_part[c] = part;
        }
    }

    // ---- completion-counter fused finalize (last block only) ----
    __shared__ bool s_last;
    __syncthreads();
    if (threadIdx.x == 0) {
        __threadfence();
        unsigned int d = atomicAdd(&g_done, 1u);
        s_last = (d == (unsigned int)(gridDim.x - 1));
    }
    __syncthreads();
    if (!s_last) return;

    __shared__ float sh[THREADS];

    // margin sum, fixed order -> bit-deterministic
    float m = 0.0f;
    for (int i = threadIdx.x; i < NB; i += THREADS) m += g_margin_part[i];
    sh[threadIdx.x] = m;
    __syncthreads();
    #pragma unroll
    for (int off = THREADS / 2; off > 0; off >>= 1) {
        if (threadIdx.x < off) sh[threadIdx.x] += sh[threadIdx.x + off];
        __syncthreads();
    }
    float margin = sh[0];
    __syncthreads();

    // alpha sum
    float a = (threadIdx.x < ALPHA_CHUNKS) ? g_alpha_part[threadIdx.x] : 0.0f;
    sh[threadIdx.x] = a;
    __syncthreads();
    #pragma unroll
    for (int off = THREADS / 2; off > 0; off >>= 1) {
        if (threadIdx.x < off) sh[threadIdx.x] += sh[threadIdx.x + off];
        __syncthreads();
    }
    float alpha_term = sh[0];

    if (threadIdx.x == 0) {
        float loss = margin * 0.875f + alpha_term * 0.125f;
        out[0] = loss;
        if (out_size > 1) out[1] = margin;
        if (out_size > 2) out[2] = alpha_term;
        // self-reset for next graph replay (stream order guarantees visibility)
        g_ticket = 0u;
        g_done   = 0u;
    }
}

extern "C" void kernel_launch(void* const* d_in, const int* in_sizes, int n_in,
                              void* d_out, int out_size)
{
    // Identify inputs robustly by element count (all distinct):
    //   sentence  8192*1024    = 8388608  (f32)
    //   all_gloss 8192*10*1024 = 83886080 (f32)
    //   alpha     2700*6*10    = 162000   (f32)
    //   sense_mask 8192*10     = 81920    (i32)
    //   sense_ids 8192         = 8192     (i32)
    const float* sentence = nullptr;
    const float* gloss    = nullptr;
    const float* alpha    = nullptr;
    const int*   mask     = nullptr;
    const int*   sids     = nullptr;
    for (int i = 0; i < n_in; ++i) {
        switch (in_sizes[i]) {
            case 8388608:  sentence = (const float*)d_in[i]; break;
            case 83886080: gloss    = (const float*)d_in[i]; break;
            case 162000:   alpha    = (const float*)d_in[i]; break;
            case 81920:    mask     = (const int*)  d_in[i]; break;
            case 8192:     sids     = (const int*)  d_in[i]; break;
            default: break;
        }
    }

    marginal_loss_fused<<<NBLOCKS, THREADS>>>(sentence, gloss, alpha, mask, sids,
                                              (float*)d_out, out_size);
}

// round 11
// speedup vs baseline: 1.0990x; 1.0050x over previous
#include <cuda_runtime.h>
#include <cstdint>
#include <math.h>

// Problem shapes (fixed by the reference)
#define NB 8192          // batch
#define SS 10            // senses
#define HH 1024          // hidden
#define THREADS 128      // 4 warps/block (smem-sized)
#define WARPS 4
#define NBLOCKS 740      // 5 blocks/SM x 148; tickets balance any residency
#define ALPHA_ROWS 16200 // 2700*6
#define ALPHA_CHUNKS 64
#define ALPHA_CHUNK 254  // 64*254 = 16256 >= 16200
#define NTICKETS (NB + ALPHA_CHUNKS)

#define STAGE_BYTES (11 * 512)   // sentence(512B) + 10 senses(512B) per j-step

// Scratch (device globals: no allocation allowed anywhere)
__device__ float g_margin_part[NB];
__device__ float g_alpha_part[ALPHA_CHUNKS];
__device__ unsigned int g_ticket;  // zero-init; self-resetting
__device__ unsigned int g_done;    // zero-init; self-resetting

#define CP_ASYNC16(dst_smem, src_gmem) \
    asm volatile("cp.async.cg.shared.global [%0], [%1], 16;" \
                 :: "r"(dst_smem), "l"(src_gmem) : "memory")
#define CP_COMMIT() asm volatile("cp.async.commit_group;" ::: "memory")
#define CP_WAIT1()  asm volatile("cp.async.wait_group 1;" ::: "memory")
#define CP_WAIT0()  asm volatile("cp.async.wait_group 0;" ::: "memory")

// Issue one j-step stage for row b into smem at smem_base (same-lane staging).
__device__ __forceinline__ void issue_stage(const float* __restrict__ sentence,
                                            const float* __restrict__ gloss,
                                            int b, int j, unsigned int smem_base, int lane)
{
    const float4* s = reinterpret_cast<const float4*>(sentence + (size_t)b * HH)
                      + j * 32 + lane;
    CP_ASYNC16(smem_base + lane * 16, s);
    const float4* g0 = reinterpret_cast<const float4*>(gloss + (size_t)b * SS * HH)
                       + j * 32 + lane;
    #pragma unroll
    for (int l = 0; l < SS; ++l)
        CP_ASYNC16(smem_base + (l + 1) * 512 + lane * 16, g0 + l * 256);
}

__global__ __launch_bounds__(THREADS)
void marginal_loss_fused(const float* __restrict__ sentence,
                         const float* __restrict__ gloss,
                         const float* __restrict__ alpha,
                         const int*   __restrict__ mask,
                         const int*   __restrict__ sids,
                         float* __restrict__ out, int out_size)
{
    const int lane = threadIdx.x & 31;
    const int warp = threadIdx.x >> 5;

    __shared__ __align__(16) char stage_buf[WARPS][2][STAGE_BYTES];

    const unsigned int base0 =
        (unsigned int)__cvta_generic_to_shared(&stage_buf[warp][0][0]);
    const unsigned int base1 =
        (unsigned int)__cvta_generic_to_shared(&stage_buf[warp][1][0]);

    // first ticket
    unsigned int t;
    if (lane == 0) t = atomicAdd(&g_ticket, 1u);
    t = __shfl_sync(0xffffffffu, t, 0);
    bool primed = false;   // true iff stage 0 of row t is already committed

    while (t < NTICKETS) {
        if (t < NB) {
            const int b = (int)t;
            if (!primed) { issue_stage(sentence, gloss, b, 0, base0, lane); CP_COMMIT(); }

            float acc[SS];
            #pragma unroll
            for (int s = 0; s < SS; ++s) acc[s] = 0.0f;

            unsigned int tn = NTICKETS;  // next ticket, fetched at j==7

            #pragma unroll
            for (int j = 0; j < 8; ++j) {
                if (j < 7) {
                    // keep one stage in flight
                    issue_stage(sentence, gloss, b, j + 1,
                                ((j + 1) & 1) ? base1 : base0, lane);
                    CP_COMMIT();
                    CP_WAIT1();           // oldest (stage j) complete
                } else {
                    // cross-row prefetch: grab next ticket, prefetch its stage 0
                    if (lane == 0) tn = atomicAdd(&g_ticket, 1u);
                    tn = __shfl_sync(0xffffffffu, tn, 0);
                    if (tn < NB) {
                        issue_stage(sentence, gloss, (int)tn, 0, base0, lane);
                        CP_COMMIT();
                        CP_WAIT1();       // stage 7 complete, next-row stage 0 in flight
                    } else {
                        CP_WAIT0();       // drain
                    }
                }

                // consume stage j (same-lane data -> no syncwarp needed)
                const float4* p = reinterpret_cast<const float4*>(
                    &stage_buf[warp][j & 1][0]);
                const float4 sv = p[lane];
                #pragma unroll
                for (int s = 0; s < SS; ++s) {
                    float4 g = p[(s + 1) * 32 + lane];
                    float d0 = sv.x - g.x + 1e-6f;
                    float d1 = sv.y - g.y + 1e-6f;
                    float d2 = sv.z - g.z + 1e-6f;
                    float d3 = sv.w - g.w + 1e-6f;
                    float a = acc[s];
                    a = fmaf(d0, d0, a);
                    a = fmaf(d1, d1, a);
                    a = fmaf(d2, d2, a);
                    a = fmaf(d3, d3, a);
                    acc[s] = a;
                }
            }

            // epilogue (next row's stage 0 loads are in flight during this)
            #pragma unroll
            for (int s = 0; s < SS; ++s) {
                float v = acc[s];
                #pragma unroll
                for (int off = 16; off > 0; off >>= 1)
                    v += __shfl_xor_sync(0xffffffffu, v, off);
                acc[s] = v;
            }

            if (lane == 0) {
                const int sid = sids[b];
                float pos  = 0.0f;
                float minv = 1e30f;   // first strict-< win == argmin first-index tie rule
                float neg  = 0.0f;
                #pragma unroll
                for (int s = 0; s < SS; ++s) {
                    float ds = sqrtf(acc[s]);
                    if (s == sid) pos = ds;
                    bool valid = (mask[b * SS + s] != 0) && (s != sid);
                    float m = valid ? ds : 10.0f;          // SENTINEL
                    if (m < minv) { minv = m; neg = ds; }  // carry REAL distance at argmin
                }
                g_margin_part[b] = fmaxf(pos - neg + 0.5f, 0.0f);
            }

            primed = (tn < NB);
            t = tn;
        } else {
            // ---- alpha chunk (plain loads; no cp.async pending here) ----
            const int c     = (int)(t - NB);
            const int start = c * ALPHA_CHUNK;
            const int end   = min(start + ALPHA_CHUNK, ALPHA_ROWS);
            float part = 0.0f;
            for (int r = start + lane; r < end; r += 32) {
                const float* __restrict__ row = alpha + (size_t)r * 10;
                float s0 = 0.0f, mx = -1e30f;
                #pragma unroll
                for (int k = 0; k < 10; ++k) {
                    float v = row[k];
                    s0 += v;
                    mx = fmaxf(mx, v);
                }
                // row_sum==0 -> tmp=ones -> max=1 -> |1-1| = 0
                part += (s0 == 0.0f) ? 0.0f : fabsf(mx - 1.0f);
            }
            #pragma unroll
            for (int off = 16; off > 0; off >>= 1)
                part += __shfl_xor_sync(0xffffffffu, part, off);
            if (lane == 0) g_alpha_part[c] = part;

            if (lane == 0) t = atomicAdd(&g_ticket, 1u);
            t = __shfl_sync(0xffffffffu, t, 0);
            primed = false;
        }
    }

    // ---- completion-counter fused finalize (last block only) ----
    __shared__ bool s_last;
    __syncthreads();
    if (threadIdx.x == 0) {
        __threadfence();
        unsigned int d = atomicAdd(&g_done, 1u);
        s_last = (d == (unsigned int)(gridDim.x - 1));
    }
    __syncthreads();
    if (!s_last) return;

    __shared__ float sh[THREADS];

    // margin sum, fixed order -> bit-deterministic
    float m = 0.0f;
    for (int i = threadIdx.x; i < NB; i += THREADS) m += g_margin_part[i];
    sh[threadIdx.x] = m;
    __syncthreads();
    #pragma unroll
    for (int off = THREADS / 2; off > 0; off >>= 1) {
        if (threadIdx.x < off) sh[threadIdx.x] += sh[threadIdx.x + off];
        __syncthreads();
    }
    float margin = sh[0];
    __syncthreads();

    // alpha sum
    float a = (threadIdx.x < ALPHA_CHUNKS) ? g_alpha_part[threadIdx.x] : 0.0f;
    sh[threadIdx.x] = a;
    __syncthreads();
    #pragma unroll
    for (int off = THREADS / 2; off > 0; off >>= 1) {
        if (threadIdx.x < off) sh[threadIdx.x] += sh[threadIdx.x + off];
        __syncthreads();
    }
    float alpha_term = sh[0];

    if (threadIdx.x == 0) {
        float loss = margin * 0.875f + alpha_term * 0.125f;
        out[0] = loss;
        if (out_size > 1) out[1] = margin;
        if (out_size > 2) out[2] = alpha_term;
        // self-reset for next graph replay (stream order guarantees visibility)
        g_ticket = 0u;
        g_done   = 0u;
    }
}

extern "C" void kernel_launch(void* const* d_in, const int* in_sizes, int n_in,
                              void* d_out, int out_size)
{
    // Identify inputs robustly by element count (all distinct):
    //   sentence  8192*1024    = 8388608  (f32)
    //   all_gloss 8192*10*1024 = 83886080 (f32)
    //   alpha     2700*6*10    = 162000   (f32)
    //   sense_mask 8192*10     = 81920    (i32)
    //   sense_ids 8192         = 8192     (i32)
    const float* sentence = nullptr;
    const float* gloss    = nullptr;
    const float* alpha    = nullptr;
    const int*   mask     = nullptr;
    const int*   sids     = nullptr;
    for (int i = 0; i < n_in; ++i) {
        switch (in_sizes[i]) {
            case 8388608:  sentence = (const float*)d_in[i]; break;
            case 83886080: gloss    = (const float*)d_in[i]; break;
            case 162000:   alpha    = (const float*)d_in[i]; break;
            case 81920:    mask     = (const int*)  d_in[i]; break;
            case 8192:     sids     = (const int*)  d_in[i]; break;
            default: break;
        }
    }

    marginal_loss_fused<<<NBLOCKS, THREADS>>>(sentence, gloss, alpha, mask, sids,
                                              (float*)d_out, out_size);
}

// round 13
// speedup vs baseline: 1.1001x; 1.0010x over previous
#include <cuda_runtime.h>
#include <cstdint>
#include <math.h>

// Problem shapes (fixed by the reference)
#define NB 8192          // batch
#define SS 10            // senses
#define HH 1024          // hidden
#define THREADS 64       // 2 warps/block (static-smem sized)
#define WARPS 2
#define NBLOCKS 740      // 5 blocks/SM x 148; tickets balance any residency
#define ALPHA_ROWS 16200 // 2700*6
#define ALPHA_CHUNKS 64
#define ALPHA_CHUNK 254  // 64*254 = 16256 >= 16200
#define NTICKETS (NB + ALPHA_CHUNKS)

#define NSTAGE 4
#define STAGE_BYTES (11 * 512)   // sentence(512B) + 10 senses(512B) per j-step

// Scratch (device globals: no allocation allowed anywhere)
__device__ float g_margin_part[NB];
__device__ float g_alpha_part[ALPHA_CHUNKS];
__device__ unsigned int g_ticket;  // zero-init; self-resetting
__device__ unsigned int g_done;    // zero-init; self-resetting

#define CP_ASYNC16(dst_smem, src_gmem) \
    asm volatile("cp.async.cg.shared.global [%0], [%1], 16;" \
                 :: "r"(dst_smem), "l"(src_gmem) : "memory")
#define CP_COMMIT() asm volatile("cp.async.commit_group;" ::: "memory")
#define CP_WAIT3()  asm volatile("cp.async.wait_group 3;" ::: "memory")
#define CP_WAIT0()  asm volatile("cp.async.wait_group 0;" ::: "memory")

// Issue one j-step stage for row b into smem at smem_base (same-lane staging).
__device__ __forceinline__ void issue_stage(const float* __restrict__ sentence,
                                            const float* __restrict__ gloss,
                                            int b, int j, unsigned int smem_base, int lane)
{
    const float4* s = reinterpret_cast<const float4*>(sentence + (size_t)b * HH)
                      + j * 32 + lane;
    CP_ASYNC16(smem_base + lane * 16, s);
    const float4* g0 = reinterpret_cast<const float4*>(gloss + (size_t)b * SS * HH)
                       + j * 32 + lane;
    #pragma unroll
    for (int l = 0; l < SS; ++l)
        CP_ASYNC16(smem_base + (l + 1) * 512 + lane * 16, g0 + l * 256);
}

__global__ __launch_bounds__(THREADS)
void marginal_loss_fused(const float* __restrict__ sentence,
                         const float* __restrict__ gloss,
                         const float* __restrict__ alpha,
                         const int*   __restrict__ mask,
                         const int*   __restrict__ sids,
                         float* __restrict__ out, int out_size)
{
    const int lane = threadIdx.x & 31;
    const int warp = threadIdx.x >> 5;

    __shared__ __align__(16) char stage_buf[WARPS][NSTAGE][STAGE_BYTES];

    const unsigned int wbase =
        (unsigned int)__cvta_generic_to_shared(&stage_buf[warp][0][0]);

    // first ticket
    unsigned int t;
    if (lane == 0) t = atomicAdd(&g_ticket, 1u);
    t = __shfl_sync(0xffffffffu, t, 0);
    bool primed = false;   // true iff stages 0..2 of row t already committed

    while (t < NTICKETS) {
        if (t < NB) {
            const int b = (int)t;
            if (!primed) {
                #pragma unroll
                for (int k = 0; k < 3; ++k) {
                    issue_stage(sentence, gloss, b, k, wbase + k * STAGE_BYTES, lane);
                    CP_COMMIT();
                }
            }

            float acc[SS];
            #pragma unroll
            for (int s = 0; s < SS; ++s) acc[s] = 0.0f;

            unsigned int tn = NTICKETS;  // next ticket, fetched at j==5

            // Pipeline invariant: one commit per iteration; before consuming
            // stage j, the 3 newest groups are stages j+1..j+3 (possibly empty)
            // -> wait_group 3 guarantees stage j's group has completed.
            #pragma unroll
            for (int j = 0; j < 8; ++j) {
                const int pj = j + 3;            // prefetch target
                if (pj < 8) {
                    issue_stage(sentence, gloss, b, pj,
                                wbase + (pj & 3) * STAGE_BYTES, lane);
                } else {
                    const int k = pj - 8;        // next row's stage 0,1,2
                    if (k == 0) {
                        if (lane == 0) tn = atomicAdd(&g_ticket, 1u);
                        tn = __shfl_sync(0xffffffffu, tn, 0);
                    }
                    if (tn < NB)
                        issue_stage(sentence, gloss, (int)tn, k,
                                    wbase + (k & 3) * STAGE_BYTES, lane);
                    // else: empty group keeps the positional invariant
                }
                CP_COMMIT();
                CP_WAIT3();

                // consume stage j (same-lane data -> no syncwarp needed)
                const float4* p = reinterpret_cast<const float4*>(
                    &stage_buf[warp][j & 3][0]);
                const float4 sv = p[lane];
                #pragma unroll
                for (int s = 0; s < SS; ++s) {
                    float4 g = p[(s + 1) * 32 + lane];
                    float d0 = sv.x - g.x + 1e-6f;
                    float d1 = sv.y - g.y + 1e-6f;
                    float d2 = sv.z - g.z + 1e-6f;
                    float d3 = sv.w - g.w + 1e-6f;
                    float a = acc[s];
                    a = fmaf(d0, d0, a);
                    a = fmaf(d1, d1, a);
                    a = fmaf(d2, d2, a);
                    a = fmaf(d3, d3, a);
                    acc[s] = a;
                }
            }

            // epilogue (next row's stages 0..2 are in flight during this)
            #pragma unroll
            for (int s = 0; s < SS; ++s) {
                float v = acc[s];
                #pragma unroll
                for (int off = 16; off > 0; off >>= 1)
                    v += __shfl_xor_sync(0xffffffffu, v, off);
                acc[s] = v;
            }

            if (lane == 0) {
                const int sid = sids[b];
                float pos  = 0.0f;
                float minv = 1e30f;   // first strict-< win == argmin first-index tie rule
                float neg  = 0.0f;
                #pragma unroll
                for (int s = 0; s < SS; ++s) {
                    float ds = sqrtf(acc[s]);
                    if (s == sid) pos = ds;
                    bool valid = (mask[b * SS + s] != 0) && (s != sid);
                    float m = valid ? ds : 10.0f;          // SENTINEL
                    if (m < minv) { minv = m; neg = ds; }  // carry REAL distance at argmin
                }
                g_margin_part[b] = fmaxf(pos - neg + 0.5f, 0.0f);
            }

            primed = (tn < NB);
            t = tn;
        } else {
            // ---- alpha chunk (plain loads; pending empty groups harmless) ----
            const int c     = (int)(t - NB);
            const int start = c * ALPHA_CHUNK;
            const int end   = min(start + ALPHA_CHUNK, ALPHA_ROWS);
            float part = 0.0f;
            for (int r = start + lane; r < end; r += 32) {
                const float* __restrict__ row = alpha + (size_t)r * 10;
                float s0 = 0.0f, mx = -1e30f;
                #pragma unroll
                for (int k = 0; k < 10; ++k) {
                    float v = row[k];
                    s0 += v;
                    mx = fmaxf(mx, v);
                }
                // row_sum==0 -> tmp=ones -> max=1 -> |1-1| = 0
                part += (s0 == 0.0f) ? 0.0f : fabsf(mx - 1.0f);
            }
            #pragma unroll
            for (int off = 16; off > 0; off >>= 1)
                part += __shfl_xor_sync(0xffffffffu, part, off);
            if (lane == 0) g_alpha_part[c] = part;

            if (lane == 0) t = atomicAdd(&g_ticket, 1u);
            t = __shfl_sync(0xffffffffu, t, 0);
            primed = false;
        }
    }

    // drain ALL outstanding cp.async groups before touching finalize / exiting
    // (never leave async smem writes pending past CTA retirement)
    CP_WAIT0();

    // ---- completion-counter fused finalize (last block only) ----
    __shared__ bool s_last;
    __syncthreads();
    if (threadIdx.x == 0) {
        __threadfence();
        unsigned int d = atomicAdd(&g_done, 1u);
        s_last = (d == (unsigned int)(gridDim.x - 1));
    }
    __syncthreads();
    if (!s_last) return;

    __shared__ float sh[THREADS];

    // margin sum, fixed order -> bit-deterministic
    float m = 0.0f;
    for (int i = threadIdx.x; i < NB; i += THREADS) m += g_margin_part[i];
    sh[threadIdx.x] = m;
    __syncthreads();
    #pragma unroll
    for (int off = THREADS / 2; off > 0; off >>= 1) {
        if (threadIdx.x < off) sh[threadIdx.x] += sh[threadIdx.x + off];
        __syncthreads();
    }
    float margin = sh[0];
    __syncthreads();

    // alpha sum
    float a = (threadIdx.x < ALPHA_CHUNKS) ? g_alpha_part[threadIdx.x] : 0.0f;
    sh[threadIdx.x] = a;
    __syncthreads();
    #pragma unroll
    for (int off = THREADS / 2; off > 0; off >>= 1) {
        if (threadIdx.x < off) sh[threadIdx.x] += sh[threadIdx.x + off];
        __syncthreads();
    }
    float alpha_term = sh[0];

    if (threadIdx.x == 0) {
        float loss = margin * 0.875f + alpha_term * 0.125f;
        out[0] = loss;
        if (out_size > 1) out[1] = margin;
        if (out_size > 2) out[2] = alpha_term;
        // self-reset for next graph replay (stream order guarantees visibility)
        g_ticket = 0u;
        g_done   = 0u;
    }
}

extern "C" void kernel_launch(void* const* d_in, const int* in_sizes, int n_in,
                              void* d_out, int out_size)
{
    // Identify inputs robustly by element count (all distinct):
    //   sentence  8192*1024    = 8388608  (f32)
    //   all_gloss 8192*10*1024 = 83886080 (f32)
    //   alpha     2700*6*10    = 162000   (f32)
    //   sense_mask 8192*10     = 81920    (i32)
    //   sense_ids 8192         = 8192     (i32)
    const float* sentence = nullptr;
    const float* gloss    = nullptr;
    const float* alpha    = nullptr;
    const int*   mask     = nullptr;
    const int*   sids     = nullptr;
    for (int i = 0; i < n_in; ++i) {
        switch (in_sizes[i]) {
            case 8388608:  sentence = (const float*)d_in[i]; break;
            case 83886080: gloss    = (const float*)d_in[i]; break;
            case 162000:   alpha    = (const float*)d_in[i]; break;
            case 81920:    mask     = (const int*)  d_in[i]; break;
            case 8192:     sids     = (const int*)  d_in[i]; break;
            default: break;
        }
    }

    marginal_loss_fused<<<NBLOCKS, THREADS>>>(sentence, gloss, alpha, mask, sids,
                                              (float*)d_out, out_size);
}